// round 7
// baseline (speedup 1.0000x reference)
#include <cuda_runtime.h>

#define LDIM  8192
#define FDIM  100
#define SEG   1024        // positions per CTA
#define SEGS  8
#define BROWS 64
#define PW    40          // words per bitplane (36 used; stride padded)
#define PWZ   36          // words actually used (tokens 0..1151)
#define NWRD  36          // 32-token word-groups per CTA
#define VP    66          // 64 vocab + plane64 (PAD, always zero) + plane65 (OOB sink)
#define NTHREADS 256
#define NWARPS 8

// cross-CTA combine scratch (zero at load; reset by finalizer each launch)
__device__ unsigned long long g_key[BROWS];
__device__ unsigned int       g_cnt[BROWS];

__device__ __forceinline__ unsigned MAJ(unsigned a, unsigned b, unsigned c) {
    return (a & b) | (a & c) | (b & c);       // single LOP3
}

// indicator word for f at position block blk (f is compile-time after unroll)
__device__ __forceinline__ unsigned IND(const unsigned* __restrict__ pl,
                                        const int* __restrict__ soff,
                                        int f, int blk)
{
    const unsigned* p = pl + soff[f] + blk + (f >> 5);
    const int r = f & 31;
    return r ? __funnelshift_r(p[0], p[1], r) : p[0];
}

// accumulate NF f's (FB..FB+NF-1) bitsliced over 32 positions; NF<=13 -> 4 planes
template<int FB, int NF>
__device__ __forceinline__ void accum(const unsigned* __restrict__ pl,
                                      const int* __restrict__ soff,
                                      int blk, unsigned cnt[4])
{
    constexpr int H0 = NF / 2, H1 = NF - H0;   // two chains for ILP, each <=7
    unsigned o0 = 0, t0 = 0, q0 = 0;
    unsigned o1 = 0, t1 = 0, q1 = 0;
    #pragma unroll
    for (int j = 0; j < H1; j++) {
        if (j < H0) {
            unsigned x = IND(pl, soff, FB + j, blk);
            unsigned c = o0 & x; o0 ^= x;
            unsigned d = t0 & c; t0 ^= c;
            q0 |= d;
        }
        {
            unsigned x = IND(pl, soff, FB + H0 + j, blk);
            unsigned c = o1 & x; o1 ^= x;
            unsigned d = t1 & c; t1 ^= c;
            q1 |= d;
        }
    }
    // merge two <=7 halves into 4 planes (sum <= 13 < 16)
    unsigned c0 = o0 & o1;            cnt[0] = o0 ^ o1;
    unsigned c1 = MAJ(t0, t1, c0);    cnt[1] = t0 ^ t1 ^ c0;
    unsigned c2 = MAJ(q0, q1, c1);    cnt[2] = q0 ^ q1 ^ c1;
    cnt[3] = c2;
}

__global__ __launch_bounds__(NTHREADS)
void finder_kernel(const int* __restrict__ expr,
                   const int* __restrict__ sub,
                   float* __restrict__ out, int B)
{
    __shared__ unsigned planes[VP * PW];          // 10.6 KB bitboards
    __shared__ int soff[FDIM];
    __shared__ unsigned xbuf[7][32][5];           // stride 5: conflict-free

    const int s    = blockIdx.x;                  // segment 0..7
    const int b    = blockIdx.y;                  // batch row
    const int tid  = threadIdx.x;
    const int lane = tid & 31;
    const int warp = tid >> 5;
    const int p0   = s * SEG;

    // ---- issue all token loads up front (coalesced, MLP<=5; hides DRAM latency) ----
    const int* erow = expr + b * LDIM;
    int tok[5];
    #pragma unroll
    for (int j = 0; j < 5; j++) {
        const int wi = warp + NWARPS * j;
        tok[j] = 65;                              // OOB sink plane (never read)
        if (wi < NWRD) {
            const int tg = p0 + wi * 32 + lane;
            if (tg < LDIM) tok[j] = erow[tg];
        }
    }
    int sval = 0;
    if (tid < FDIM) sval = sub[b * FDIM + tid];

    // ---- zero readable bitplanes (0..64): 65 x 9 uint4 ----
    for (int i = tid; i < 65 * (PWZ / 4); i += NTHREADS) {
        const int pl = i / (PWZ / 4), wq = i % (PWZ / 4);
        *(uint4*)&planes[pl * PW + wq * 4] = make_uint4(0, 0, 0, 0);
    }
    if (tid < FDIM) soff[tid] = (sval == 0 ? 64 : sval) * PW;   // PAD -> zero plane
    __syncthreads();

    // ---- build bitboards: one MATCH per 32-token word, leader stores full mask ----
    #pragma unroll
    for (int j = 0; j < 5; j++) {
        const int wi = warp + NWARPS * j;         // warp-uniform guard
        if (wi < NWRD) {
            const unsigned m = __match_any_sync(0xFFFFFFFFu, tok[j]);
            if (lane == (__ffs(m) - 1))
                planes[tok[j] * PW + wi] = m;     // plain STS, complete mask
        }
    }
    __syncthreads();

    // ---- bitsliced accumulation: warp = f-group, lane = position block ----
    unsigned cnt[4];
    switch (warp) {                               // 4x13 + 4x12 = 100 f's
        case 0:  accum< 0, 13>(planes, soff, lane, cnt); break;
        case 1:  accum<13, 13>(planes, soff, lane, cnt); break;
        case 2:  accum<26, 13>(planes, soff, lane, cnt); break;
        case 3:  accum<39, 13>(planes, soff, lane, cnt); break;
        case 4:  accum<52, 12>(planes, soff, lane, cnt); break;
        case 5:  accum<64, 12>(planes, soff, lane, cnt); break;
        case 6:  accum<76, 12>(planes, soff, lane, cnt); break;
        default: accum<88, 12>(planes, soff, lane, cnt); break;
    }
    if (warp) {
        xbuf[warp - 1][lane][0] = cnt[0];
        xbuf[warp - 1][lane][1] = cnt[1];
        xbuf[warp - 1][lane][2] = cnt[2];
        xbuf[warp - 1][lane][3] = cnt[3];
    }
    __syncthreads();

    if (warp == 0) {
        // preload all partials (MLP), then ripple-add 7 x 4-plane numbers
        unsigned d[7][4];
        #pragma unroll
        for (int pq = 0; pq < 7; pq++)
            #pragma unroll
            for (int k = 0; k < 4; k++) d[pq][k] = xbuf[pq][lane][k];

        unsigned r[7] = {cnt[0], cnt[1], cnt[2], cnt[3], 0, 0, 0};
        #pragma unroll
        for (int pq = 0; pq < 7; pq++) {
            unsigned a, c = 0;
            #pragma unroll
            for (int k = 0; k < 4; k++) {
                a = r[k]; r[k] = a ^ d[pq][k] ^ c; c = MAJ(a, d[pq][k], c);
            }
            a = r[4]; r[4] = a ^ c; c = a & c;
            a = r[5]; r[5] = a ^ c; c = a & c;
            r[6] |= c;                            // total <= 100 < 128
        }

        // bitplane max over 32 positions + first index
        unsigned m = 0xFFFFFFFFu, score = 0;
        #pragma unroll
        for (int k = 6; k >= 0; k--) {
            unsigned t  = m & r[k];
            unsigned nz = (t != 0u);
            m = nz ? t : m;
            score += nz << k;
        }
        const int pos = p0 + lane * 32 + (__ffs(m) - 1);
        unsigned long long key = ((unsigned long long)score << 32)
                               | (unsigned)(0x7FFFFFFF - pos);

        #pragma unroll
        for (int off = 16; off; off >>= 1) {
            unsigned long long o = __shfl_xor_sync(0xFFFFFFFFu, key, off);
            if (o > key) key = o;
        }

        if (lane == 0) {
            atomicMax(&g_key[b], key);            // relaxed; ordered by release below
            unsigned arrived;
            asm volatile("atom.release.gpu.global.add.u32 %0, [%1], %2;"
                         : "=r"(arrived) : "l"(&g_cnt[b]), "r"(1u) : "memory");
            if (arrived == SEGS - 1) {            // last segment CTA for this row
                unsigned long long k;
                asm volatile("atom.acquire.gpu.global.max.u64 %0, [%1], %2;"
                             : "=l"(k) : "l"(&g_key[b]), "l"(0ULL) : "memory");
                out[b]     = (float)(0x7FFFFFFFu - (unsigned)(k & 0xFFFFFFFFu));
                out[B + b] = (float)(unsigned)(k >> 32);
                g_key[b] = 0ULL;                  // reset for next graph replay
                g_cnt[b] = 0u;
            }
        }
    }
}

extern "C" void kernel_launch(void* const* d_in, const int* in_sizes, int n_in,
                              void* d_out, int out_size)
{
    const int* expr = (const int*)d_in[0];   // [B, 8192] int32
    const int* sub  = (const int*)d_in[1];   // [B, 100]  int32
    float* out = (float*)d_out;              // [2*B] float32: positions then scores

    const int B = in_sizes[1] / FDIM;        // 64
    dim3 grid(SEGS, B);
    finder_kernel<<<grid, NTHREADS>>>(expr, sub, out, B);
}

// round 8
// speedup vs baseline: 1.2007x; 1.2007x over previous
#include <cuda_runtime.h>

#define LDIM  8192
#define FDIM  100
#define SEG   1024        // positions per CTA
#define SEGS  8
#define BROWS 64
#define PW    40          // words per bitplane (36 used; stride padded)
#define PWZ   36          // words actually used (tokens 0..1151)
#define VP    65          // 64 vocab planes + always-zero plane for PAD
#define NTHREADS 256
#define NG    288         // int4 token groups per CTA (tokens 0..1151)

// cross-CTA combine scratch (g_cnt zero at load; reset by finalizer each launch;
// g_part slots are written before ever being read, no reset needed)
__device__ unsigned long long g_part[BROWS][SEGS];
__device__ unsigned int       g_cnt[BROWS];

__device__ __forceinline__ unsigned MAJ(unsigned a, unsigned b, unsigned c) {
    return (a & b) | (a & c) | (b & c);       // single LOP3
}

// indicator word for f at position block blk (f compile-time after unroll)
__device__ __forceinline__ unsigned IND(const unsigned* __restrict__ pl,
                                        const int* __restrict__ soff,
                                        int f, int blk)
{
    const unsigned* p = pl + soff[f] + blk + (f >> 5);
    const int r = f & 31;
    return r ? __funnelshift_r(p[0], p[1], r) : p[0];
}

// accumulate NF f's (FB..FB+NF-1) bitsliced over 32 positions; NF<=13 -> 4 planes
template<int FB, int NF>
__device__ __forceinline__ void accum(const unsigned* __restrict__ pl,
                                      const int* __restrict__ soff,
                                      int blk, unsigned cnt[4])
{
    constexpr int H0 = NF / 2, H1 = NF - H0;   // two chains for ILP, each <=7
    unsigned o0 = 0, t0 = 0, q0 = 0;
    unsigned o1 = 0, t1 = 0, q1 = 0;
    #pragma unroll
    for (int j = 0; j < H1; j++) {
        if (j < H0) {
            unsigned x = IND(pl, soff, FB + j, blk);
            unsigned c = o0 & x; o0 ^= x;
            unsigned d = t0 & c; t0 ^= c;
            q0 |= d;
        }
        {
            unsigned x = IND(pl, soff, FB + H0 + j, blk);
            unsigned c = o1 & x; o1 ^= x;
            unsigned d = t1 & c; t1 ^= c;
            q1 |= d;
        }
    }
    // merge two <=7 halves into 4 planes (sum <= 13 < 16)
    unsigned c0 = o0 & o1;            cnt[0] = o0 ^ o1;
    unsigned c1 = MAJ(t0, t1, c0);    cnt[1] = t0 ^ t1 ^ c0;
    unsigned c2 = MAJ(q0, q1, c1);    cnt[2] = q0 ^ q1 ^ c1;
    cnt[3] = c2;
}

__global__ __launch_bounds__(NTHREADS)
void finder_kernel(const int* __restrict__ expr,
                   const int* __restrict__ sub,
                   float* __restrict__ out, int B)
{
    __shared__ unsigned planes[VP * PW];          // 10.4 KB bitboards
    __shared__ unsigned xbuf[7][32][4];           // 16B-aligned rows: vec4 conflict-free
    __shared__ int soff[FDIM];

    const int s    = blockIdx.x;                  // segment 0..7
    const int b    = blockIdx.y;                  // batch row
    const int tid  = threadIdx.x;
    const int lane = tid & 31;
    const int warp = tid >> 5;
    const int p0   = s * SEG;

    // ---- front-load gmem (overlaps shared zeroing); R4-proven int4 pattern ----
    const int* erow = expr + b * LDIM;
    int4 v0 = *(const int4*)(erow + p0 + 4 * tid);           // always in range
    int4 v1; bool h1 = false;
    if (tid < NG - NTHREADS) {                               // groups 256..287
        const int tg = p0 + 4 * (tid + NTHREADS);
        if (tg < LDIM) { v1 = *(const int4*)(erow + tg); h1 = true; }
    }
    int sval = 0;
    if (tid < FDIM) sval = sub[b * FDIM + tid];

    // ---- zero bitplanes: 65 planes x 9 uint4 ----
    for (int i = tid; i < VP * (PWZ / 4); i += NTHREADS) {
        const int pl = i / (PWZ / 4), wq = i % (PWZ / 4);
        *(uint4*)&planes[pl * PW + wq * 4] = make_uint4(0, 0, 0, 0);
    }
    if (tid < FDIM) soff[tid] = (sval == 0 ? 64 : sval) * PW;   // PAD -> zero plane
    __syncthreads();

    // ---- scatter bitboard bits (atomicOr; tail tokens beyond L stay 0) ----
    {
        const int tl = 4 * tid, w = tl >> 5;
        atomicOr(&planes[v0.x * PW + w], 1u << ((tl    ) & 31));
        atomicOr(&planes[v0.y * PW + w], 1u << ((tl + 1) & 31));
        atomicOr(&planes[v0.z * PW + w], 1u << ((tl + 2) & 31));
        atomicOr(&planes[v0.w * PW + w], 1u << ((tl + 3) & 31));
    }
    if (h1) {
        const int tl = 4 * (tid + NTHREADS), w = tl >> 5;
        atomicOr(&planes[v1.x * PW + w], 1u << ((tl    ) & 31));
        atomicOr(&planes[v1.y * PW + w], 1u << ((tl + 1) & 31));
        atomicOr(&planes[v1.z * PW + w], 1u << ((tl + 2) & 31));
        atomicOr(&planes[v1.w * PW + w], 1u << ((tl + 3) & 31));
    }
    __syncthreads();

    // ---- bitsliced accumulation: warp = f-group, lane = position block ----
    unsigned cnt[4];
    switch (warp) {                               // 4x13 + 4x12 = 100 f's
        case 0:  accum< 0, 13>(planes, soff, lane, cnt); break;
        case 1:  accum<13, 13>(planes, soff, lane, cnt); break;
        case 2:  accum<26, 13>(planes, soff, lane, cnt); break;
        case 3:  accum<39, 13>(planes, soff, lane, cnt); break;
        case 4:  accum<52, 12>(planes, soff, lane, cnt); break;
        case 5:  accum<64, 12>(planes, soff, lane, cnt); break;
        case 6:  accum<76, 12>(planes, soff, lane, cnt); break;
        default: accum<88, 12>(planes, soff, lane, cnt); break;
    }
    if (warp)
        *(uint4*)&xbuf[warp - 1][lane][0] = make_uint4(cnt[0], cnt[1], cnt[2], cnt[3]);
    __syncthreads();

    if (warp == 0) {
        // preload all partials with LDS.128 (conflict-free), then ripple-add
        uint4 d[7];
        #pragma unroll
        for (int pq = 0; pq < 7; pq++) d[pq] = *(const uint4*)&xbuf[pq][lane][0];

        unsigned r[7] = {cnt[0], cnt[1], cnt[2], cnt[3], 0, 0, 0};
        #pragma unroll
        for (int pq = 0; pq < 7; pq++) {
            unsigned a, c;
            a = r[0]; r[0] = a ^ d[pq].x;        c = a & d[pq].x;
            a = r[1]; r[1] = a ^ d[pq].y ^ c;    c = MAJ(a, d[pq].y, c);
            a = r[2]; r[2] = a ^ d[pq].z ^ c;    c = MAJ(a, d[pq].z, c);
            a = r[3]; r[3] = a ^ d[pq].w ^ c;    c = MAJ(a, d[pq].w, c);
            a = r[4]; r[4] = a ^ c;              c = a & c;
            a = r[5]; r[5] = a ^ c;              c = a & c;
            r[6] |= c;                           // total <= 100 < 128
        }

        // bitplane max over 32 positions + first index
        unsigned m = 0xFFFFFFFFu, score = 0;
        #pragma unroll
        for (int k = 6; k >= 0; k--) {
            unsigned t  = m & r[k];
            unsigned nz = (t != 0u);
            m = nz ? t : m;
            score += nz << k;
        }
        const int pos = p0 + lane * 32 + (__ffs(m) - 1);
        unsigned long long key = ((unsigned long long)score << 32)
                               | (unsigned)(0x7FFFFFFF - pos);

        #pragma unroll
        for (int off = 16; off; off >>= 1) {
            unsigned long long o = __shfl_xor_sync(0xFFFFFFFFu, key, off);
            if (o > key) key = o;
        }

        // ---- cheap tail: slot store + one counter atomic + last-CTA gather ----
        unsigned arrived = 0;
        if (lane == 0) {
            g_part[b][s] = key;                            // plain STG
            asm volatile("atom.acq_rel.gpu.global.add.u32 %0, [%1], %2;"
                         : "=r"(arrived) : "l"(&g_cnt[b]), "r"(1u) : "memory");
        }
        arrived = __shfl_sync(0xFFFFFFFFu, arrived, 0);
        if (arrived == SEGS - 1) {                         // last segment CTA
            unsigned long long k = (lane < SEGS) ? g_part[b][lane] : 0ULL;
            #pragma unroll
            for (int off = 4; off; off >>= 1) {
                unsigned long long o = __shfl_xor_sync(0xFFFFFFFFu, k, off);
                if (o > k) k = o;
            }
            if (lane == 0) {
                out[b]     = (float)(0x7FFFFFFFu - (unsigned)(k & 0xFFFFFFFFu));
                out[B + b] = (float)(unsigned)(k >> 32);
                g_cnt[b] = 0u;                             // reset for next replay
            }
        }
    }
}

extern "C" void kernel_launch(void* const* d_in, const int* in_sizes, int n_in,
                              void* d_out, int out_size)
{
    const int* expr = (const int*)d_in[0];   // [B, 8192] int32
    const int* sub  = (const int*)d_in[1];   // [B, 100]  int32
    float* out = (float*)d_out;              // [2*B] float32: positions then scores

    const int B = in_sizes[1] / FDIM;        // 64
    dim3 grid(SEGS, B);
    finder_kernel<<<grid, NTHREADS>>>(expr, sub, out, B);
}

// round 9
// speedup vs baseline: 1.2316x; 1.0257x over previous
#include <cuda_runtime.h>

#define LDIM  8192
#define FDIM  100
#define SEG   1024        // positions per CTA
#define SEGS  8
#define BROWS 64
#define PW    40          // words per bitplane (36 used; stride padded)
#define PWZ   36          // words actually used (tokens 0..1151)
#define VP    65          // 64 vocab planes + always-zero plane for PAD
#define NTHREADS 320      // 10 warps = 10 f-groups of 10
#define NQ    10
#define NG    288         // int4 token groups per CTA (tokens 0..1151), 1 per thread

// cross-CTA combine scratch (g_cnt zero at load; reset by finalizer each launch;
// g_part slots are written before ever being read, no reset needed)
__device__ unsigned long long g_part[BROWS][SEGS];
__device__ unsigned int       g_cnt[BROWS];

__device__ __forceinline__ unsigned MAJ(unsigned a, unsigned b, unsigned c) {
    return (a & b) | (a & c) | (b & c);       // single LOP3
}

// indicator word for f at position block blk (f compile-time after unroll)
__device__ __forceinline__ unsigned IND(const unsigned* __restrict__ pl,
                                        const int* __restrict__ soff,
                                        int f, int blk)
{
    const unsigned* p = pl + soff[f] + blk + (f >> 5);
    const int r = f & 31;
    return r ? __funnelshift_r(p[0], p[1], r) : p[0];
}

// accumulate 10 f's (FB..FB+9) bitsliced over 32 positions -> 4 planes (sum<=10)
template<int FB>
__device__ __forceinline__ void accum(const unsigned* __restrict__ pl,
                                      const int* __restrict__ soff,
                                      int blk, unsigned cnt[4])
{
    unsigned o0 = 0, t0 = 0, q0 = 0;          // two 5-deep chains for ILP
    unsigned o1 = 0, t1 = 0, q1 = 0;
    #pragma unroll
    for (int j = 0; j < 5; j++) {
        {
            unsigned x = IND(pl, soff, FB + j, blk);
            unsigned c = o0 & x; o0 ^= x;
            unsigned d = t0 & c; t0 ^= c;
            q0 |= d;
        }
        {
            unsigned x = IND(pl, soff, FB + 5 + j, blk);
            unsigned c = o1 & x; o1 ^= x;
            unsigned d = t1 & c; t1 ^= c;
            q1 |= d;
        }
    }
    // merge two <=5 halves into 4 planes (sum <= 10 < 16)
    unsigned c0 = o0 & o1;            cnt[0] = o0 ^ o1;
    unsigned c1 = MAJ(t0, t1, c0);    cnt[1] = t0 ^ t1 ^ c0;
    unsigned c2 = MAJ(q0, q1, c1);    cnt[2] = q0 ^ q1 ^ c1;
    cnt[3] = c2;
}

__global__ __launch_bounds__(NTHREADS)
void finder_kernel(const int* __restrict__ expr,
                   const int* __restrict__ sub,
                   float* __restrict__ out, int B)
{
    __shared__ unsigned planes[VP * PW];          // 10.4 KB bitboards
    __shared__ unsigned xbuf[NQ - 1][32][4];      // 16B rows: vec4 conflict-free
    __shared__ int soff[FDIM];

    const int s    = blockIdx.x;                  // segment 0..7
    const int b    = blockIdx.y;                  // batch row
    const int tid  = threadIdx.x;
    const int lane = tid & 31;
    const int warp = tid >> 5;
    const int p0   = s * SEG;

    // ---- front-load gmem (overlaps shared zeroing); one int4 per thread ----
    const int* erow = expr + b * LDIM;
    int4 v0; bool h0 = false;
    if (tid < NG) {
        const int tg = p0 + 4 * tid;
        if (tg < LDIM) { v0 = *(const int4*)(erow + tg); h0 = true; }
    }
    int sval = 0;
    if (tid < FDIM) sval = sub[b * FDIM + tid];

    // ---- zero bitplanes linearly (incl. stride padding): 650 uint4, no div/mod ----
    for (int i = tid; i < VP * PW / 4; i += NTHREADS)
        ((uint4*)planes)[i] = make_uint4(0, 0, 0, 0);
    if (tid < FDIM) soff[tid] = (sval == 0 ? 64 : sval) * PW;   // PAD -> zero plane
    __syncthreads();

    // ---- scatter bitboard bits (4 atomicOr per thread, balanced) ----
    if (h0) {
        const int tl = 4 * tid, w = tl >> 5;
        atomicOr(&planes[v0.x * PW + w], 1u << ((tl    ) & 31));
        atomicOr(&planes[v0.y * PW + w], 1u << ((tl + 1) & 31));
        atomicOr(&planes[v0.z * PW + w], 1u << ((tl + 2) & 31));
        atomicOr(&planes[v0.w * PW + w], 1u << ((tl + 3) & 31));
    }
    __syncthreads();

    // ---- bitsliced accumulation: warp = f-group (10 f's), lane = position block ----
    unsigned cnt[4];
    switch (warp) {
        case 0:  accum< 0>(planes, soff, lane, cnt); break;
        case 1:  accum<10>(planes, soff, lane, cnt); break;
        case 2:  accum<20>(planes, soff, lane, cnt); break;
        case 3:  accum<30>(planes, soff, lane, cnt); break;
        case 4:  accum<40>(planes, soff, lane, cnt); break;
        case 5:  accum<50>(planes, soff, lane, cnt); break;
        case 6:  accum<60>(planes, soff, lane, cnt); break;
        case 7:  accum<70>(planes, soff, lane, cnt); break;
        case 8:  accum<80>(planes, soff, lane, cnt); break;
        default: accum<90>(planes, soff, lane, cnt); break;
    }
    if (warp)
        *(uint4*)&xbuf[warp - 1][lane][0] = make_uint4(cnt[0], cnt[1], cnt[2], cnt[3]);
    __syncthreads();

    if (warp == 0) {
        // preload all partials with LDS.128 (conflict-free), then ripple-add
        uint4 d[NQ - 1];
        #pragma unroll
        for (int pq = 0; pq < NQ - 1; pq++) d[pq] = *(const uint4*)&xbuf[pq][lane][0];

        unsigned r[7] = {cnt[0], cnt[1], cnt[2], cnt[3], 0, 0, 0};
        #pragma unroll
        for (int pq = 0; pq < NQ - 1; pq++) {
            unsigned a, c;
            a = r[0]; r[0] = a ^ d[pq].x;        c = a & d[pq].x;
            a = r[1]; r[1] = a ^ d[pq].y ^ c;    c = MAJ(a, d[pq].y, c);
            a = r[2]; r[2] = a ^ d[pq].z ^ c;    c = MAJ(a, d[pq].z, c);
            a = r[3]; r[3] = a ^ d[pq].w ^ c;    c = MAJ(a, d[pq].w, c);
            a = r[4]; r[4] = a ^ c;              c = a & c;
            a = r[5]; r[5] = a ^ c;              c = a & c;
            r[6] |= c;                           // total <= 100 < 128
        }

        // bitplane max over 32 positions + first index
        unsigned m = 0xFFFFFFFFu, score = 0;
        #pragma unroll
        for (int k = 6; k >= 0; k--) {
            unsigned t  = m & r[k];
            unsigned nz = (t != 0u);
            m = nz ? t : m;
            score += nz << k;
        }
        const int pos = p0 + lane * 32 + (__ffs(m) - 1);
        unsigned long long key = ((unsigned long long)score << 32)
                               | (unsigned)(0x7FFFFFFF - pos);

        #pragma unroll
        for (int off = 16; off; off >>= 1) {
            unsigned long long o = __shfl_xor_sync(0xFFFFFFFFu, key, off);
            if (o > key) key = o;
        }

        // ---- cheap tail: slot store + one counter atomic + last-CTA gather ----
        unsigned arrived = 0;
        if (lane == 0) {
            g_part[b][s] = key;                            // plain STG
            asm volatile("atom.acq_rel.gpu.global.add.u32 %0, [%1], %2;"
                         : "=r"(arrived) : "l"(&g_cnt[b]), "r"(1u) : "memory");
        }
        arrived = __shfl_sync(0xFFFFFFFFu, arrived, 0);
        if (arrived == SEGS - 1) {                         // last segment CTA
            unsigned long long k = (lane < SEGS) ? g_part[b][lane] : 0ULL;
            #pragma unroll
            for (int off = 4; off; off >>= 1) {
                unsigned long long o = __shfl_xor_sync(0xFFFFFFFFu, k, off);
                if (o > k) k = o;
            }
            if (lane == 0) {
                out[b]     = (float)(0x7FFFFFFFu - (unsigned)(k & 0xFFFFFFFFu));
                out[B + b] = (float)(unsigned)(k >> 32);
                g_cnt[b] = 0u;                             // reset for next replay
            }
        }
    }
}

extern "C" void kernel_launch(void* const* d_in, const int* in_sizes, int n_in,
                              void* d_out, int out_size)
{
    const int* expr = (const int*)d_in[0];   // [B, 8192] int32
    const int* sub  = (const int*)d_in[1];   // [B, 100]  int32
    float* out = (float*)d_out;              // [2*B] float32: positions then scores

    const int B = in_sizes[1] / FDIM;        // 64
    dim3 grid(SEGS, B);
    finder_kernel<<<grid, NTHREADS>>>(expr, sub, out, B);
}